// round 1
// baseline (speedup 1.0000x reference)
#include <cuda_runtime.h>
#include <cuda_bf16.h>

// Problem constants (from reference_code)
#define N_NODES 50000
#define N_EDGES 800000
#define IN_F 64
#define OUT_F 64

// Scratch for support = x @ W  (50000 * 64 floats = 12.8 MB)
__device__ float g_support[N_NODES * OUT_F];

// ---------------------------------------------------------------------------
// Kernel 1: out[n][j] = bias[j]   (vectorized float4)
// out has N_NODES*OUT_F floats = 800000 float4
// ---------------------------------------------------------------------------
__global__ void init_bias_kernel(float4* __restrict__ out,
                                 const float4* __restrict__ bias4,
                                 int n_vec4) {
    int i = blockIdx.x * blockDim.x + threadIdx.x;
    if (i < n_vec4) {
        // OUT_F = 64 floats = 16 float4 per row
        out[i] = bias4[i & 15];
    }
}

// ---------------------------------------------------------------------------
// Kernel 2: support = x @ W
// Block: (64, 8) = 512 threads. Each block handles 8 node rows.
// W (64x64) staged in smem once per block; x rows staged in smem.
// Output write fully coalesced (tx = output column).
// ---------------------------------------------------------------------------
__global__ __launch_bounds__(512) void gemm_kernel(
    const float* __restrict__ x,
    const float* __restrict__ w,
    float* __restrict__ sup,
    int n_nodes) {
    __shared__ float sw[IN_F * OUT_F];   // 16 KB
    __shared__ float sx[8 * IN_F];       // 2 KB

    int tx = threadIdx.x;   // 0..63  -> output column
    int ty = threadIdx.y;   // 0..7   -> node within block
    int t  = ty * 64 + tx;

    // Stage W
    #pragma unroll
    for (int i = t; i < IN_F * OUT_F; i += 512) sw[i] = w[i];

    int node = blockIdx.x * 8 + ty;
    // Stage x rows (guarded)
    if (node < n_nodes) sx[ty * IN_F + tx] = x[node * IN_F + tx];
    __syncthreads();

    if (node >= n_nodes) return;

    const float* xr = &sx[ty * IN_F];
    float acc = 0.0f;
    #pragma unroll
    for (int k = 0; k < IN_F; ++k)
        acc = fmaf(xr[k], sw[k * OUT_F + tx], acc);

    sup[node * OUT_F + tx] = acc;
}

// ---------------------------------------------------------------------------
// Kernel 3: scatter-add over edges.
// 16 threads per edge; each thread handles 4 consecutive output features.
// Gather support[col] via float4 (L2-resident), scale by edge_val,
// atomicAdd into out[row].
// ---------------------------------------------------------------------------
__global__ __launch_bounds__(256) void scatter_kernel(
    const int* __restrict__ edge_row,
    const int* __restrict__ edge_col,
    const float* __restrict__ edge_val,
    const float* __restrict__ sup,
    float* __restrict__ out,
    int n_edges) {
    long long tid = (long long)blockIdx.x * blockDim.x + threadIdx.x;
    int e = (int)(tid >> 4);
    if (e >= n_edges) return;
    int l = (int)(tid & 15);          // which float4 within the 64-wide row

    int r = edge_row[e];
    int c = edge_col[e];
    float v = edge_val[e];

    float4 s = *reinterpret_cast<const float4*>(sup + (long long)c * OUT_F + l * 4);

    float* o = out + (long long)r * OUT_F + l * 4;
    atomicAdd(o + 0, v * s.x);
    atomicAdd(o + 1, v * s.y);
    atomicAdd(o + 2, v * s.z);
    atomicAdd(o + 3, v * s.w);
}

// ---------------------------------------------------------------------------
// Launch: inputs in order  x, edge_row, edge_col, edge_val, weight, bias
// ---------------------------------------------------------------------------
extern "C" void kernel_launch(void* const* d_in, const int* in_sizes, int n_in,
                              void* d_out, int out_size) {
    const float* x        = (const float*)d_in[0];
    const int*   edge_row = (const int*)  d_in[1];
    const int*   edge_col = (const int*)  d_in[2];
    const float* edge_val = (const float*)d_in[3];
    const float* weight   = (const float*)d_in[4];
    const float* bias     = (const float*)d_in[5];
    float* out = (float*)d_out;

    int n_nodes = in_sizes[0] / IN_F;
    int n_edges = in_sizes[1];

    float* sup;
    cudaGetSymbolAddress((void**)&sup, g_support);

    // 1) out = broadcast(bias)
    {
        int n_vec4 = (n_nodes * OUT_F) / 4;
        int threads = 256;
        int blocks = (n_vec4 + threads - 1) / threads;
        init_bias_kernel<<<blocks, threads>>>(
            (float4*)out, (const float4*)bias, n_vec4);
    }

    // 2) support = x @ W
    {
        dim3 block(64, 8);
        int blocks = (n_nodes + 7) / 8;
        gemm_kernel<<<blocks, block>>>(x, weight, sup, n_nodes);
    }

    // 3) scatter-add edges
    {
        long long total_threads = (long long)n_edges * 16;
        int threads = 256;
        int blocks = (int)((total_threads + threads - 1) / threads);
        scatter_kernel<<<blocks, threads>>>(
            edge_row, edge_col, edge_val, sup, out, n_edges);
    }
}

// round 2
// speedup vs baseline: 2.6085x; 2.6085x over previous
#include <cuda_runtime.h>
#include <cuda_bf16.h>

#define N_NODES 50000
#define N_EDGES 800000
#define IN_F 64
#define OUT_F 64

// Scratch for support = x @ W  (50000 * 64 floats = 12.8 MB)
__device__ float g_support[N_NODES * OUT_F];

// ---------------------------------------------------------------------------
// Kernel 1: fused  support = x @ W   AND   out = broadcast(bias)
// Block: 256 threads computes a 64-node x 64-col tile; each thread owns a
// 4x4 register patch -> 16 FFMA per 2-ish LDS (FMA-bound, ~12us floor).
// ---------------------------------------------------------------------------
__global__ __launch_bounds__(256) void gemm_bias_kernel(
    const float* __restrict__ x,
    const float* __restrict__ w,
    const float* __restrict__ bias,
    float* __restrict__ sup,
    float* __restrict__ out,
    int n_nodes) {
    __shared__ float sw[IN_F * OUT_F];        // 16 KB, w[k*64 + col]
    __shared__ float sx[64 * 65];             // 64 rows padded to 65 (bank-conflict-free)

    int t  = threadIdx.x;
    int tx = t & 15;    // col group: cols tx*4 .. tx*4+3
    int ty = t >> 4;    // row group: rows ty*4 .. ty*4+3

    // Stage W once
    #pragma unroll 4
    for (int i = t; i < IN_F * OUT_F; i += 256) sw[i] = w[i];

    // Bias for this thread's 4 columns
    float4 b4 = *reinterpret_cast<const float4*>(bias + tx * 4);

    int base = blockIdx.x * 64;

    // Stage x tile (rows base..base+63), padded stride 65
    #pragma unroll 4
    for (int i = t; i < 64 * 64; i += 256) {
        int r = i >> 6;
        int k = i & 63;
        int node = base + r;
        sx[r * 65 + k] = (node < n_nodes) ? x[node * IN_F + k] : 0.0f;
    }
    __syncthreads();

    float acc[4][4] = {};
    #pragma unroll
    for (int k = 0; k < IN_F; ++k) {
        float xv[4];
        #pragma unroll
        for (int r = 0; r < 4; ++r) xv[r] = sx[(ty * 4 + r) * 65 + k];
        float4 wv = *reinterpret_cast<const float4*>(&sw[k * OUT_F + tx * 4]);
        #pragma unroll
        for (int r = 0; r < 4; ++r) {
            acc[r][0] = fmaf(xv[r], wv.x, acc[r][0]);
            acc[r][1] = fmaf(xv[r], wv.y, acc[r][1]);
            acc[r][2] = fmaf(xv[r], wv.z, acc[r][2]);
            acc[r][3] = fmaf(xv[r], wv.w, acc[r][3]);
        }
    }

    #pragma unroll
    for (int r = 0; r < 4; ++r) {
        int node = base + ty * 4 + r;
        if (node < n_nodes) {
            float4 a = make_float4(acc[r][0], acc[r][1], acc[r][2], acc[r][3]);
            *reinterpret_cast<float4*>(sup + (long long)node * OUT_F + tx * 4) = a;
            *reinterpret_cast<float4*>(out + (long long)node * OUT_F + tx * 4) = b4;
        }
    }
}

// ---------------------------------------------------------------------------
// Kernel 2: scatter-add over edges with vectorized red.global.add.v4.f32
// 16 threads per edge; each thread handles one float4 of the 64-wide row.
// ---------------------------------------------------------------------------
__global__ __launch_bounds__(256) void scatter_kernel(
    const int* __restrict__ edge_row,
    const int* __restrict__ edge_col,
    const float* __restrict__ edge_val,
    const float* __restrict__ sup,
    float* __restrict__ out,
    int n_edges) {
    long long tid = (long long)blockIdx.x * blockDim.x + threadIdx.x;
    int e = (int)(tid >> 4);
    if (e >= n_edges) return;
    int l = (int)(tid & 15);

    int r   = __ldg(edge_row + e);
    int c   = __ldg(edge_col + e);
    float v = __ldg(edge_val + e);

    float4 s = *reinterpret_cast<const float4*>(sup + (long long)c * OUT_F + l * 4);

    float* o = out + (long long)r * OUT_F + l * 4;
    asm volatile(
        "red.global.add.v4.f32 [%0], {%1, %2, %3, %4};"
        :: "l"(o), "f"(v * s.x), "f"(v * s.y), "f"(v * s.z), "f"(v * s.w)
        : "memory");
}

// ---------------------------------------------------------------------------
// Launch: inputs in order  x, edge_row, edge_col, edge_val, weight, bias
// ---------------------------------------------------------------------------
extern "C" void kernel_launch(void* const* d_in, const int* in_sizes, int n_in,
                              void* d_out, int out_size) {
    const float* x        = (const float*)d_in[0];
    const int*   edge_row = (const int*)  d_in[1];
    const int*   edge_col = (const int*)  d_in[2];
    const float* edge_val = (const float*)d_in[3];
    const float* weight   = (const float*)d_in[4];
    const float* bias     = (const float*)d_in[5];
    float* out = (float*)d_out;

    int n_nodes = in_sizes[0] / IN_F;
    int n_edges = in_sizes[1];

    float* sup;
    cudaGetSymbolAddress((void**)&sup, g_support);

    // 1) support = x @ W ; out = bias (fused)
    {
        int blocks = (n_nodes + 63) / 64;
        gemm_bias_kernel<<<blocks, 256>>>(x, weight, bias, sup, out, n_nodes);
    }

    // 2) scatter-add edges (vector RED)
    {
        long long total_threads = (long long)n_edges * 16;
        int threads = 256;
        int blocks = (int)((total_threads + threads - 1) / threads);
        scatter_kernel<<<blocks, threads>>>(
            edge_row, edge_col, edge_val, sup, out, n_edges);
    }
}

// round 3
// speedup vs baseline: 2.7382x; 1.0497x over previous
#include <cuda_runtime.h>
#include <cuda_bf16.h>

#define N_NODES 50000
#define N_EDGES 800000
#define IN_F 64
#define OUT_F 64
#define EPT 4   // edges per thread-slot in scatter

// Scratch for support = x @ W  (50000 * 64 floats = 12.8 MB)
__device__ float g_support[N_NODES * OUT_F];

// ---------------------------------------------------------------------------
// Kernel 1: fused  support = x @ W   AND   out = broadcast(bias)
// 256 threads per block, 64x64 tile, 4x4 register patch per thread.
// ---------------------------------------------------------------------------
__global__ __launch_bounds__(256) void gemm_bias_kernel(
    const float* __restrict__ x,
    const float* __restrict__ w,
    const float* __restrict__ bias,
    float* __restrict__ sup,
    float* __restrict__ out,
    int n_nodes) {
    __shared__ float sw[IN_F * OUT_F];        // 16 KB, w[k*64 + col]
    __shared__ float sx[64 * 65];             // padded stride 65

    int t  = threadIdx.x;
    int tx = t & 15;    // col group: cols tx*4 .. tx*4+3
    int ty = t >> 4;    // row group: rows ty*4 .. ty*4+3

    #pragma unroll 4
    for (int i = t; i < IN_F * OUT_F; i += 256) sw[i] = w[i];

    float4 b4 = *reinterpret_cast<const float4*>(bias + tx * 4);

    int base = blockIdx.x * 64;

    #pragma unroll 4
    for (int i = t; i < 64 * 64; i += 256) {
        int r = i >> 6;
        int k = i & 63;
        int node = base + r;
        sx[r * 65 + k] = (node < n_nodes) ? x[node * IN_F + k] : 0.0f;
    }
    __syncthreads();

    float acc[4][4] = {};
    #pragma unroll
    for (int k = 0; k < IN_F; ++k) {
        float xv[4];
        #pragma unroll
        for (int r = 0; r < 4; ++r) xv[r] = sx[(ty * 4 + r) * 65 + k];
        float4 wv = *reinterpret_cast<const float4*>(&sw[k * OUT_F + tx * 4]);
        #pragma unroll
        for (int r = 0; r < 4; ++r) {
            acc[r][0] = fmaf(xv[r], wv.x, acc[r][0]);
            acc[r][1] = fmaf(xv[r], wv.y, acc[r][1]);
            acc[r][2] = fmaf(xv[r], wv.z, acc[r][2]);
            acc[r][3] = fmaf(xv[r], wv.w, acc[r][3]);
        }
    }

    #pragma unroll
    for (int r = 0; r < 4; ++r) {
        int node = base + ty * 4 + r;
        if (node < n_nodes) {
            float4 a = make_float4(acc[r][0], acc[r][1], acc[r][2], acc[r][3]);
            *reinterpret_cast<float4*>(sup + (long long)node * OUT_F + tx * 4) = a;
            *reinterpret_cast<float4*>(out + (long long)node * OUT_F + tx * 4) = b4;
        }
    }
}

// ---------------------------------------------------------------------------
// Kernel 2: scatter-add, 4 edges per thread-slot, software pipelined for MLP.
// tid -> (slot, l): 16 threads (l=0..15) cover one edge's 64 floats.
// slot s handles edges  s, s+n_slots, s+2*n_slots, s+3*n_slots  (coalesced
// index loads across consecutive slots).
// ---------------------------------------------------------------------------
__global__ __launch_bounds__(256) void scatter_kernel(
    const int* __restrict__ edge_row,
    const int* __restrict__ edge_col,
    const float* __restrict__ edge_val,
    const float* __restrict__ sup,
    float* __restrict__ out,
    int n_edges, int n_slots) {
    long long tid = (long long)blockIdx.x * blockDim.x + threadIdx.x;
    int l    = (int)(tid & 15);
    int slot = (int)(tid >> 4);
    if (slot >= n_slots) return;

    int   e[EPT];
    int   r[EPT], c[EPT];
    float v[EPT];
    bool  ok[EPT];

    // Phase 1: all index loads in flight
    #pragma unroll
    for (int i = 0; i < EPT; ++i) {
        e[i]  = slot + i * n_slots;
        ok[i] = (e[i] < n_edges);
        int ee = ok[i] ? e[i] : 0;
        r[i] = __ldg(edge_row + ee);
        c[i] = __ldg(edge_col + ee);
        v[i] = __ldg(edge_val + ee);
    }

    // Phase 2: all gathers in flight (4 independent L2 loads per thread)
    float4 s[EPT];
    #pragma unroll
    for (int i = 0; i < EPT; ++i) {
        s[i] = *reinterpret_cast<const float4*>(
            sup + (long long)c[i] * OUT_F + l * 4);
    }

    // Phase 3: scale + vector RED
    #pragma unroll
    for (int i = 0; i < EPT; ++i) {
        if (ok[i]) {
            float* o = out + (long long)r[i] * OUT_F + l * 4;
            asm volatile(
                "red.global.add.v4.f32 [%0], {%1, %2, %3, %4};"
                :: "l"(o), "f"(v[i] * s[i].x), "f"(v[i] * s[i].y),
                   "f"(v[i] * s[i].z), "f"(v[i] * s[i].w)
                : "memory");
        }
    }
}

// ---------------------------------------------------------------------------
// Launch: inputs in order  x, edge_row, edge_col, edge_val, weight, bias
// ---------------------------------------------------------------------------
extern "C" void kernel_launch(void* const* d_in, const int* in_sizes, int n_in,
                              void* d_out, int out_size) {
    const float* x        = (const float*)d_in[0];
    const int*   edge_row = (const int*)  d_in[1];
    const int*   edge_col = (const int*)  d_in[2];
    const float* edge_val = (const float*)d_in[3];
    const float* weight   = (const float*)d_in[4];
    const float* bias     = (const float*)d_in[5];
    float* out = (float*)d_out;

    int n_nodes = in_sizes[0] / IN_F;
    int n_edges = in_sizes[1];

    float* sup;
    cudaGetSymbolAddress((void**)&sup, g_support);

    // 1) support = x @ W ; out = bias (fused)
    {
        int blocks = (n_nodes + 63) / 64;
        gemm_bias_kernel<<<blocks, 256>>>(x, weight, bias, sup, out, n_nodes);
    }

    // 2) scatter-add edges, 4 edges per slot
    {
        int n_slots = (n_edges + EPT - 1) / EPT;
        long long total_threads = (long long)n_slots * 16;
        int threads = 256;
        int blocks = (int)((total_threads + threads - 1) / threads);
        scatter_kernel<<<blocks, threads>>>(
            edge_row, edge_col, edge_val, sup, out, n_edges, n_slots);
    }
}